// round 3
// baseline (speedup 1.0000x reference)
#include <cuda_runtime.h>
#include <math.h>

#define NMAX  100000
#define FIN   128
#define C1    16
#define C2    8
#define NPB   64   // nodes per block in gemm1

// Scratch (device globals: allocation-free per harness rules)
__device__ float g_deg [NMAX];
__device__ float g_dinv[NMAX];
__device__ float g_hw1 [NMAX * C1];
__device__ float g_h1  [NMAX * C1];
__device__ float g_hw2 [NMAX * C2];
__device__ float g_h2  [NMAX * C2];
__device__ float g_z   [NMAX];

// Vectorized fp32 reduction (sm_90+): one 16B RED, no return.
__device__ __forceinline__ void red_add_v4(float* addr, float a, float b,
                                           float c, float d) {
    asm volatile(
        "{\n\t"
        ".reg .u64 ga;\n\t"
        "cvta.to.global.u64 ga, %0;\n\t"
        "red.global.add.v4.f32 [ga], {%1, %2, %3, %4};\n\t"
        "}"
        :: "l"(addr), "f"(a), "f"(b), "f"(c), "f"(d) : "memory");
}

// ---------------------------------------------------------------------------
// K0: zero degree accumulator (graph replays need fresh state every call)
__global__ void k_init(int n) {
    int i = blockIdx.x * blockDim.x + threadIdx.x;
    if (i < n) g_deg[i] = 0.0f;
}

// K1: degree scatter over E edges (dst row of edge_index)
__global__ void k_deg(const int* __restrict__ dst, int E) {
    int e = blockIdx.x * blockDim.x + threadIdx.x;
    if (e < E) atomicAdd(&g_deg[dst[e]], 1.0f);
}

// K2: dinv = rsqrt(deg + 1)  (+1 = self loop; always > 0)
__global__ void k_dinv(int n) {
    int i = blockIdx.x * blockDim.x + threadIdx.x;
    if (i < n) g_dinv[i] = rsqrtf(g_deg[i] + 1.0f);
}

// K3: hw1 = x @ W1 ; h1 = b1 + dinv^2 * hw1  (self-loop + bias folded)
// Block: 256 threads stage 64 x-rows (32KB) coalesced, 4 threads/node K-split.
__global__ __launch_bounds__(256) void k_gemm1(const float* __restrict__ x,
                                               const float* __restrict__ W1,
                                               const float* __restrict__ b1,
                                               int n) {
    __shared__ float xs[NPB * FIN];   // 32KB
    __shared__ float Ws[FIN * C1];    // 8KB
    for (int t = threadIdx.x; t < FIN * C1; t += 256) Ws[t] = W1[t];

    int base = blockIdx.x * NPB;
    int rows = n - base; if (rows > NPB) rows = NPB;

    // coalesced tile load
    const float4* xg = reinterpret_cast<const float4*>(x + (size_t)base * FIN);
    float4* xs4 = reinterpret_cast<float4*>(xs);
    int total4 = rows * (FIN / 4);
    for (int t = threadIdx.x; t < total4; t += 256) xs4[t] = xg[t];
    __syncthreads();

    int j = threadIdx.x >> 2;   // node within tile
    int q = threadIdx.x & 3;    // K quarter
    float acc[C1];
#pragma unroll
    for (int c = 0; c < C1; c++) acc[c] = 0.0f;

    if (j < rows) {
        const float* xr = &xs[j * FIN + q * 32];
#pragma unroll 8
        for (int k = 0; k < 32; k++) {
            float v = xr[k];
            const float* wr = &Ws[(q * 32 + k) * C1];
#pragma unroll
            for (int c = 0; c < C1; c++) acc[c] += v * wr[c];
        }
    }
    // combine K quarters across lanes (j,q) -> lanes differ only in q bits
#pragma unroll
    for (int c = 0; c < C1; c++) {
        acc[c] += __shfl_xor_sync(0xffffffffu, acc[c], 1);
        acc[c] += __shfl_xor_sync(0xffffffffu, acc[c], 2);
    }
    if (q == 0 && j < rows) {
        int i = base + j;
        float dv = g_dinv[i];
        float w  = dv * dv;
        float4* o1 = reinterpret_cast<float4*>(&g_hw1[i * C1]);
        float4* o2 = reinterpret_cast<float4*>(&g_h1[i * C1]);
#pragma unroll
        for (int g = 0; g < 4; g++) {
            float4 v = make_float4(acc[g*4+0], acc[g*4+1], acc[g*4+2], acc[g*4+3]);
            o1[g] = v;
            o2[g] = make_float4(b1[g*4+0] + w * v.x, b1[g*4+1] + w * v.y,
                                b1[g*4+2] + w * v.z, b1[g*4+3] + w * v.w);
        }
    }
}

// K4: edge scatter layer 1 — 1 thread/edge, 4x (float4 gather + red.v4)
__global__ void k_scat1(const int* __restrict__ src,
                        const int* __restrict__ dst, int E) {
    int e = blockIdx.x * blockDim.x + threadIdx.x;
    if (e >= E) return;
    int s = src[e];
    int d = dst[e];
    float w = g_dinv[s] * g_dinv[d];
    const float4* hs = reinterpret_cast<const float4*>(&g_hw1[s * C1]);
    float* hd = &g_h1[d * C1];
#pragma unroll
    for (int g = 0; g < 4; g++) {
        float4 v = hs[g];
        red_add_v4(hd + g * 4, w * v.x, w * v.y, w * v.z, w * v.w);
    }
}

// K5: hw2 = h1 @ W2 ; h2 = b2 + dinv^2 * hw2
__global__ void k_gemm2(const float* __restrict__ W2,
                        const float* __restrict__ b2, int n) {
    __shared__ float Ws[C1 * C2];
    for (int t = threadIdx.x; t < C1 * C2; t += blockDim.x) Ws[t] = W2[t];
    __syncthreads();
    int i = blockIdx.x * blockDim.x + threadIdx.x;
    if (i >= n) return;
    float acc[C2];
#pragma unroll
    for (int c = 0; c < C2; c++) acc[c] = 0.0f;
    const float4* h4 = reinterpret_cast<const float4*>(&g_h1[i * C1]);
#pragma unroll
    for (int k4 = 0; k4 < 4; k4++) {
        float4 v = h4[k4];
#pragma unroll
        for (int c = 0; c < C2; c++) {
            acc[c] += v.x * Ws[(k4*4+0) * C2 + c] + v.y * Ws[(k4*4+1) * C2 + c]
                    + v.z * Ws[(k4*4+2) * C2 + c] + v.w * Ws[(k4*4+3) * C2 + c];
        }
    }
    float dv = g_dinv[i];
    float w  = dv * dv;
    float4* o1 = reinterpret_cast<float4*>(&g_hw2[i * C2]);
    float4* o2 = reinterpret_cast<float4*>(&g_h2[i * C2]);
#pragma unroll
    for (int g = 0; g < 2; g++) {
        float4 v = make_float4(acc[g*4+0], acc[g*4+1], acc[g*4+2], acc[g*4+3]);
        o1[g] = v;
        o2[g] = make_float4(b2[g*4+0] + w * v.x, b2[g*4+1] + w * v.y,
                            b2[g*4+2] + w * v.z, b2[g*4+3] + w * v.w);
    }
}

// K6: edge scatter layer 2 — 1 thread/edge, 2x (float4 gather + red.v4)
__global__ void k_scat2(const int* __restrict__ src,
                        const int* __restrict__ dst, int E) {
    int e = blockIdx.x * blockDim.x + threadIdx.x;
    if (e >= E) return;
    int s = src[e];
    int d = dst[e];
    float w = g_dinv[s] * g_dinv[d];
    const float4* hs = reinterpret_cast<const float4*>(&g_hw2[s * C2]);
    float* hd = &g_h2[d * C2];
#pragma unroll
    for (int g = 0; g < 2; g++) {
        float4 v = hs[g];
        red_add_v4(hd + g * 4, w * v.x, w * v.y, w * v.z, w * v.w);
    }
}

// K7: z = sigmoid(h2 @ Wl + bl)
__global__ void k_head(const float* __restrict__ Wl,
                       const float* __restrict__ bl, int n) {
    int i = blockIdx.x * blockDim.x + threadIdx.x;
    if (i >= n) return;
    float acc = bl[0];
    const float4* h4 = reinterpret_cast<const float4*>(&g_h2[i * C2]);
    float4 a = h4[0], b = h4[1];
    acc += a.x * Wl[0] + a.y * Wl[1] + a.z * Wl[2] + a.w * Wl[3]
         + b.x * Wl[4] + b.y * Wl[5] + b.z * Wl[6] + b.w * Wl[7];
    g_z[i] = 1.0f / (1.0f + expf(-acc));
}

// K8: pred[p] = z[pe[p,0]] * z[pe[p,1]]
__global__ void k_pred(const int* __restrict__ pe,
                       float* __restrict__ out, int P) {
    int p = blockIdx.x * blockDim.x + threadIdx.x;
    if (p >= P) return;
    int2 ab = reinterpret_cast<const int2*>(pe)[p];
    out[p] = g_z[ab.x] * g_z[ab.y];
}

extern "C" void kernel_launch(void* const* d_in, const int* in_sizes, int n_in,
                              void* d_out, int out_size) {
    const float* x   = (const float*)d_in[0];
    const int*   ei  = (const int*)d_in[1];
    const int*   pe  = (const int*)d_in[2];
    const float* W1  = (const float*)d_in[3];
    const float* b1  = (const float*)d_in[4];
    const float* W2  = (const float*)d_in[5];
    const float* b2  = (const float*)d_in[6];
    const float* Wl  = (const float*)d_in[7];
    const float* bl  = (const float*)d_in[8];
    float* out = (float*)d_out;

    int n = in_sizes[0] / FIN;
    int E = in_sizes[1] / 2;
    int P = in_sizes[2] / 2;

    const int* src = ei;
    const int* dst = ei + E;

    const int T = 256;

    k_init <<<(n + T - 1) / T, T>>>(n);
    k_deg  <<<(E + T - 1) / T, T>>>(dst, E);
    k_dinv <<<(n + T - 1) / T, T>>>(n);
    k_gemm1<<<(n + NPB - 1) / NPB, 256>>>(x, W1, b1, n);
    k_scat1<<<(E + T - 1) / T, T>>>(src, dst, E);
    k_gemm2<<<(n + T - 1) / T, T>>>(W2, b2, n);
    k_scat2<<<(E + T - 1) / T, T>>>(src, dst, E);
    k_head <<<(n + T - 1) / T, T>>>(Wl, bl, n);
    k_pred <<<(P + T - 1) / T, T>>>(pe, out, P);
}

// round 4
// speedup vs baseline: 1.4226x; 1.4226x over previous
#include <cuda_runtime.h>
#include <math.h>

#define NMAX  100000
#define EMAX  3200000
#define FIN   128
#define C1    16
#define C2    8
#define NPB   64   // nodes per block in gemm1

// Scratch (device globals: allocation-free per harness rules)
__device__ float g_deg [NMAX];
__device__ float g_dinv[NMAX];
__device__ float g_w   [EMAX];          // per-edge norm weight
__device__ float g_hw1 [NMAX * C1];
__device__ float g_h1  [NMAX * C1];
__device__ float g_hw2 [NMAX * C2];
__device__ float g_h2  [NMAX * C2];
__device__ float g_z   [NMAX];

// Vectorized fp32 reduction (sm_90+): one 16B RED, no return.
__device__ __forceinline__ void red_add_v4(float* addr, float a, float b,
                                           float c, float d) {
    asm volatile(
        "{\n\t"
        ".reg .u64 ga;\n\t"
        "cvta.to.global.u64 ga, %0;\n\t"
        "red.global.add.v4.f32 [ga], {%1, %2, %3, %4};\n\t"
        "}"
        :: "l"(addr), "f"(a), "f"(b), "f"(c), "f"(d) : "memory");
}

// ---------------------------------------------------------------------------
// K0: zero degree accumulator (graph replays need fresh state every call)
__global__ void k_init(int n) {
    int i = blockIdx.x * blockDim.x + threadIdx.x;
    if (i < n) g_deg[i] = 0.0f;
}

// K1: degree scatter over E edges (dst row of edge_index)
__global__ void k_deg(const int* __restrict__ dst, int E) {
    int e = blockIdx.x * blockDim.x + threadIdx.x;
    if (e < E) atomicAdd(&g_deg[dst[e]], 1.0f);
}

// K2: dinv = rsqrt(deg + 1)  (+1 = self loop; always > 0)
__global__ void k_dinv(int n) {
    int i = blockIdx.x * blockDim.x + threadIdx.x;
    if (i < n) g_dinv[i] = rsqrtf(g_deg[i] + 1.0f);
}

// K2b: per-edge weight w_e = dinv[src]*dinv[dst] (loaded coalesced in scatters)
__global__ void k_wedge(const int* __restrict__ src,
                        const int* __restrict__ dst, int E) {
    int e = blockIdx.x * blockDim.x + threadIdx.x;
    if (e < E) g_w[e] = g_dinv[src[e]] * g_dinv[dst[e]];
}

// K3: hw1 = x @ W1 ; h1 = b1 + dinv^2 * hw1  (self-loop + bias folded)
// Warp = 8 nodes x 4 lanes; lane q owns channels 4q..4q+3. Padded smem tile.
#define XPAD 33   // float4 row stride (32 data + 1 pad) -> conflict-free
__global__ __launch_bounds__(256) void k_gemm1(const float* __restrict__ x,
                                               const float* __restrict__ W1,
                                               const float* __restrict__ b1,
                                               int n) {
    __shared__ float4 xs4[NPB * XPAD];   // 33.8KB
    __shared__ float4 Ws4[FIN * 4];      // 8KB: Ws4[k*4+q] = W1[k][4q..4q+3]

    for (int t = threadIdx.x; t < FIN * 4; t += 256)
        Ws4[t] = reinterpret_cast<const float4*>(W1)[t];

    int base = blockIdx.x * NPB;
    int rows = n - base; if (rows > NPB) rows = NPB;

    // coalesced tile load, padded store
    const float4* xg = reinterpret_cast<const float4*>(x + (size_t)base * FIN);
    int total4 = rows * (FIN / 4);
    for (int t = threadIdx.x; t < total4; t += 256)
        xs4[(t >> 5) * XPAD + (t & 31)] = xg[t];
    __syncthreads();

    int j = threadIdx.x >> 2;   // node within tile (0..63)
    int q = threadIdx.x & 3;    // channel group
    float4 acc = make_float4(0.f, 0.f, 0.f, 0.f);

    const float4* xr = &xs4[j * XPAD];
#pragma unroll
    for (int k4 = 0; k4 < FIN / 4; k4++) {
        float4 v = xr[k4];
        float4 w0 = Ws4[(k4 * 4 + 0) * 4 + q];
        float4 w1 = Ws4[(k4 * 4 + 1) * 4 + q];
        float4 w2 = Ws4[(k4 * 4 + 2) * 4 + q];
        float4 w3 = Ws4[(k4 * 4 + 3) * 4 + q];
        acc.x += v.x * w0.x + v.y * w1.x + v.z * w2.x + v.w * w3.x;
        acc.y += v.x * w0.y + v.y * w1.y + v.z * w2.y + v.w * w3.y;
        acc.z += v.x * w0.z + v.y * w1.z + v.z * w2.z + v.w * w3.z;
        acc.w += v.x * w0.w + v.y * w1.w + v.z * w2.w + v.w * w3.w;
    }

    if (j < rows) {
        int i = base + j;
        float dv = g_dinv[i];
        float w  = dv * dv;
        float4 bb = reinterpret_cast<const float4*>(b1)[q];
        reinterpret_cast<float4*>(g_hw1)[i * 4 + q] = acc;
        reinterpret_cast<float4*>(g_h1)[i * 4 + q] =
            make_float4(bb.x + w * acc.x, bb.y + w * acc.y,
                        bb.z + w * acc.z, bb.w + w * acc.w);
    }
}

// K4: edge scatter layer 1 — 1 thread/edge, 4x (float4 gather + red.v4)
__global__ void k_scat1(const int* __restrict__ src,
                        const int* __restrict__ dst, int E) {
    int e = blockIdx.x * blockDim.x + threadIdx.x;
    if (e >= E) return;
    int s = src[e];
    int d = dst[e];
    float w = g_w[e];
    const float4* hs = reinterpret_cast<const float4*>(&g_hw1[s * C1]);
    float* hd = &g_h1[d * C1];
#pragma unroll
    for (int g = 0; g < 4; g++) {
        float4 v = hs[g];
        red_add_v4(hd + g * 4, w * v.x, w * v.y, w * v.z, w * v.w);
    }
}

// K5: hw2 = h1 @ W2 ; h2 = b2 + dinv^2 * hw2
__global__ void k_gemm2(const float* __restrict__ W2,
                        const float* __restrict__ b2, int n) {
    __shared__ float Ws[C1 * C2];
    for (int t = threadIdx.x; t < C1 * C2; t += blockDim.x) Ws[t] = W2[t];
    __syncthreads();
    int i = blockIdx.x * blockDim.x + threadIdx.x;
    if (i >= n) return;
    float acc[C2];
#pragma unroll
    for (int c = 0; c < C2; c++) acc[c] = 0.0f;
    const float4* h4 = reinterpret_cast<const float4*>(&g_h1[i * C1]);
#pragma unroll
    for (int k4 = 0; k4 < 4; k4++) {
        float4 v = h4[k4];
#pragma unroll
        for (int c = 0; c < C2; c++) {
            acc[c] += v.x * Ws[(k4*4+0) * C2 + c] + v.y * Ws[(k4*4+1) * C2 + c]
                    + v.z * Ws[(k4*4+2) * C2 + c] + v.w * Ws[(k4*4+3) * C2 + c];
        }
    }
    float dv = g_dinv[i];
    float w  = dv * dv;
    float4* o1 = reinterpret_cast<float4*>(&g_hw2[i * C2]);
    float4* o2 = reinterpret_cast<float4*>(&g_h2[i * C2]);
#pragma unroll
    for (int g = 0; g < 2; g++) {
        float4 v = make_float4(acc[g*4+0], acc[g*4+1], acc[g*4+2], acc[g*4+3]);
        o1[g] = v;
        o2[g] = make_float4(b2[g*4+0] + w * v.x, b2[g*4+1] + w * v.y,
                            b2[g*4+2] + w * v.z, b2[g*4+3] + w * v.w);
    }
}

// K6: edge scatter layer 2 — 1 thread/edge, 2x (float4 gather + red.v4)
__global__ void k_scat2(const int* __restrict__ src,
                        const int* __restrict__ dst, int E) {
    int e = blockIdx.x * blockDim.x + threadIdx.x;
    if (e >= E) return;
    int s = src[e];
    int d = dst[e];
    float w = g_w[e];
    const float4* hs = reinterpret_cast<const float4*>(&g_hw2[s * C2]);
    float* hd = &g_h2[d * C2];
#pragma unroll
    for (int g = 0; g < 2; g++) {
        float4 v = hs[g];
        red_add_v4(hd + g * 4, w * v.x, w * v.y, w * v.z, w * v.w);
    }
}

// K7: z = sigmoid(h2 @ Wl + bl)
__global__ void k_head(const float* __restrict__ Wl,
                       const float* __restrict__ bl, int n) {
    int i = blockIdx.x * blockDim.x + threadIdx.x;
    if (i >= n) return;
    float acc = bl[0];
    const float4* h4 = reinterpret_cast<const float4*>(&g_h2[i * C2]);
    float4 a = h4[0], b = h4[1];
    acc += a.x * Wl[0] + a.y * Wl[1] + a.z * Wl[2] + a.w * Wl[3]
         + b.x * Wl[4] + b.y * Wl[5] + b.z * Wl[6] + b.w * Wl[7];
    g_z[i] = 1.0f / (1.0f + expf(-acc));
}

// K8: pred[p] = z[pe[p,0]] * z[pe[p,1]]
__global__ void k_pred(const int* __restrict__ pe,
                       float* __restrict__ out, int P) {
    int p = blockIdx.x * blockDim.x + threadIdx.x;
    if (p >= P) return;
    int2 ab = reinterpret_cast<const int2*>(pe)[p];
    out[p] = g_z[ab.x] * g_z[ab.y];
}

extern "C" void kernel_launch(void* const* d_in, const int* in_sizes, int n_in,
                              void* d_out, int out_size) {
    const float* x   = (const float*)d_in[0];
    const int*   ei  = (const int*)d_in[1];
    const int*   pe  = (const int*)d_in[2];
    const float* W1  = (const float*)d_in[3];
    const float* b1  = (const float*)d_in[4];
    const float* W2  = (const float*)d_in[5];
    const float* b2  = (const float*)d_in[6];
    const float* Wl  = (const float*)d_in[7];
    const float* bl  = (const float*)d_in[8];
    float* out = (float*)d_out;

    int n = in_sizes[0] / FIN;
    int E = in_sizes[1] / 2;
    int P = in_sizes[2] / 2;
    if (E > EMAX) E = EMAX;  // g_w capacity (spec: E = 3.2M exactly)

    const int* src = ei;
    const int* dst = ei + E;

    const int T = 256;

    k_init <<<(n + T - 1) / T, T>>>(n);
    k_deg  <<<(E + T - 1) / T, T>>>(dst, E);
    k_dinv <<<(n + T - 1) / T, T>>>(n);
    k_wedge<<<(E + T - 1) / T, T>>>(src, dst, E);
    k_gemm1<<<(n + NPB - 1) / NPB, 256>>>(x, W1, b1, n);
    k_scat1<<<(E + T - 1) / T, T>>>(src, dst, E);
    k_gemm2<<<(n + T - 1) / T, T>>>(W2, b2, n);
    k_scat2<<<(E + T - 1) / T, T>>>(src, dst, E);
    k_head <<<(n + T - 1) / T, T>>>(Wl, bl, n);
    k_pred <<<(P + T - 1) / T, T>>>(pe, out, P);
}

// round 5
// speedup vs baseline: 1.4304x; 1.0055x over previous
#include <cuda_runtime.h>
#include <math.h>

#define NMAX  100000
#define EMAX  3200000
#define FIN   128
#define C1    16
#define C2    8
#define NPB   64   // nodes per block in gemm1

// Scratch (device globals: allocation-free per harness rules)
__device__ float g_deg [NMAX];
__device__ float g_dinv[NMAX];
__device__ float g_w   [EMAX];          // per-edge norm weight (written by scat1)
__device__ float g_hw1 [NMAX * C1];
__device__ float g_h1  [NMAX * C1];
__device__ float g_hw2 [NMAX * C2];
__device__ float g_h2  [NMAX * C2];
__device__ float g_z   [NMAX];

// Vectorized fp32 reduction (sm_90+): one 16B RED, no return.
__device__ __forceinline__ void red_add_v4(float* addr, float a, float b,
                                           float c, float d) {
    asm volatile(
        "{\n\t"
        ".reg .u64 ga;\n\t"
        "cvta.to.global.u64 ga, %0;\n\t"
        "red.global.add.v4.f32 [ga], {%1, %2, %3, %4};\n\t"
        "}"
        :: "l"(addr), "f"(a), "f"(b), "f"(c), "f"(d) : "memory");
}

// ---------------------------------------------------------------------------
// K0: zero degree accumulator (graph replays need fresh state every call)
__global__ void k_init(int n) {
    int i = blockIdx.x * blockDim.x + threadIdx.x;
    if (i < n) g_deg[i] = 0.0f;
}

// K1: degree scatter, 4 edges/thread via int4
__global__ void k_deg(const int* __restrict__ dst, int E) {
    int t = blockIdx.x * blockDim.x + threadIdx.x;
    int e0 = t * 4;
    if (e0 + 3 < E) {
        int4 d4 = reinterpret_cast<const int4*>(dst)[t];
        atomicAdd(&g_deg[d4.x], 1.0f);
        atomicAdd(&g_deg[d4.y], 1.0f);
        atomicAdd(&g_deg[d4.z], 1.0f);
        atomicAdd(&g_deg[d4.w], 1.0f);
    } else {
        for (int e = e0; e < E; e++) atomicAdd(&g_deg[dst[e]], 1.0f);
    }
}

// K3: hw1 = x @ W1 ; h1 = b1 + dinv^2 * hw1 ; also emits g_dinv.
// Warp = 8 nodes x 4 lanes; lane q owns channels 4q..4q+3. Padded smem tile.
#define XPAD 33   // float4 row stride (32 data + 1 pad) -> conflict-free
__global__ __launch_bounds__(256) void k_gemm1(const float* __restrict__ x,
                                               const float* __restrict__ W1,
                                               const float* __restrict__ b1,
                                               int n) {
    __shared__ float4 xs4[NPB * XPAD];   // 33.8KB
    __shared__ float4 Ws4[FIN * 4];      // 8KB: Ws4[k*4+q] = W1[k][4q..4q+3]

    for (int t = threadIdx.x; t < FIN * 4; t += 256)
        Ws4[t] = reinterpret_cast<const float4*>(W1)[t];

    int base = blockIdx.x * NPB;
    int rows = n - base; if (rows > NPB) rows = NPB;

    // coalesced tile load, padded store
    const float4* xg = reinterpret_cast<const float4*>(x + (size_t)base * FIN);
    int total4 = rows * (FIN / 4);
    for (int t = threadIdx.x; t < total4; t += 256)
        xs4[(t >> 5) * XPAD + (t & 31)] = xg[t];
    __syncthreads();

    int j = threadIdx.x >> 2;   // node within tile (0..63)
    int q = threadIdx.x & 3;    // channel group
    float4 acc = make_float4(0.f, 0.f, 0.f, 0.f);

    const float4* xr = &xs4[j * XPAD];
#pragma unroll
    for (int k4 = 0; k4 < FIN / 4; k4++) {
        float4 v = xr[k4];
        float4 w0 = Ws4[(k4 * 4 + 0) * 4 + q];
        float4 w1 = Ws4[(k4 * 4 + 1) * 4 + q];
        float4 w2 = Ws4[(k4 * 4 + 2) * 4 + q];
        float4 w3 = Ws4[(k4 * 4 + 3) * 4 + q];
        acc.x += v.x * w0.x + v.y * w1.x + v.z * w2.x + v.w * w3.x;
        acc.y += v.x * w0.y + v.y * w1.y + v.z * w2.y + v.w * w3.y;
        acc.z += v.x * w0.z + v.y * w1.z + v.z * w2.z + v.w * w3.z;
        acc.w += v.x * w0.w + v.y * w1.w + v.z * w2.w + v.w * w3.w;
    }

    if (j < rows) {
        int i = base + j;
        float dv = rsqrtf(g_deg[i] + 1.0f);   // self-loop included
        if (q == 0) g_dinv[i] = dv;
        float w = dv * dv;
        float4 bb = reinterpret_cast<const float4*>(b1)[q];
        reinterpret_cast<float4*>(g_hw1)[i * 4 + q] = acc;
        reinterpret_cast<float4*>(g_h1)[i * 4 + q] =
            make_float4(bb.x + w * acc.x, bb.y + w * acc.y,
                        bb.z + w * acc.z, bb.w + w * acc.w);
    }
}

// K4: edge scatter layer 1 — 1 thread/edge; computes + stores w for scat2.
__global__ void k_scat1(const int* __restrict__ src,
                        const int* __restrict__ dst, int E) {
    int e = blockIdx.x * blockDim.x + threadIdx.x;
    if (e >= E) return;
    int s = src[e];
    int d = dst[e];
    float w = g_dinv[s] * g_dinv[d];
    g_w[e] = w;
    const float4* hs = reinterpret_cast<const float4*>(&g_hw1[s * C1]);
    float* hd = &g_h1[d * C1];
#pragma unroll
    for (int g = 0; g < 4; g++) {
        float4 v = hs[g];
        red_add_v4(hd + g * 4, w * v.x, w * v.y, w * v.z, w * v.w);
    }
}

// K5: hw2 = h1 @ W2 ; h2 = b2 + dinv^2 * hw2
__global__ void k_gemm2(const float* __restrict__ W2,
                        const float* __restrict__ b2, int n) {
    __shared__ float Ws[C1 * C2];
    for (int t = threadIdx.x; t < C1 * C2; t += blockDim.x) Ws[t] = W2[t];
    __syncthreads();
    int i = blockIdx.x * blockDim.x + threadIdx.x;
    if (i >= n) return;
    float acc[C2];
#pragma unroll
    for (int c = 0; c < C2; c++) acc[c] = 0.0f;
    const float4* h4 = reinterpret_cast<const float4*>(&g_h1[i * C1]);
#pragma unroll
    for (int k4 = 0; k4 < 4; k4++) {
        float4 v = h4[k4];
#pragma unroll
        for (int c = 0; c < C2; c++) {
            acc[c] += v.x * Ws[(k4*4+0) * C2 + c] + v.y * Ws[(k4*4+1) * C2 + c]
                    + v.z * Ws[(k4*4+2) * C2 + c] + v.w * Ws[(k4*4+3) * C2 + c];
        }
    }
    float dv = g_dinv[i];
    float w  = dv * dv;
    float4* o1 = reinterpret_cast<float4*>(&g_hw2[i * C2]);
    float4* o2 = reinterpret_cast<float4*>(&g_h2[i * C2]);
#pragma unroll
    for (int g = 0; g < 2; g++) {
        float4 v = make_float4(acc[g*4+0], acc[g*4+1], acc[g*4+2], acc[g*4+3]);
        o1[g] = v;
        o2[g] = make_float4(b2[g*4+0] + w * v.x, b2[g*4+1] + w * v.y,
                            b2[g*4+2] + w * v.z, b2[g*4+3] + w * v.w);
    }
}

// K6: edge scatter layer 2 — 1 thread/edge, reuses precomputed w
__global__ void k_scat2(const int* __restrict__ src,
                        const int* __restrict__ dst, int E) {
    int e = blockIdx.x * blockDim.x + threadIdx.x;
    if (e >= E) return;
    int s = src[e];
    int d = dst[e];
    float w = g_w[e];
    const float4* hs = reinterpret_cast<const float4*>(&g_hw2[s * C2]);
    float* hd = &g_h2[d * C2];
#pragma unroll
    for (int g = 0; g < 2; g++) {
        float4 v = hs[g];
        red_add_v4(hd + g * 4, w * v.x, w * v.y, w * v.z, w * v.w);
    }
}

// K7: z = sigmoid(h2 @ Wl + bl)
__global__ void k_head(const float* __restrict__ Wl,
                       const float* __restrict__ bl, int n) {
    int i = blockIdx.x * blockDim.x + threadIdx.x;
    if (i >= n) return;
    float acc = bl[0];
    const float4* h4 = reinterpret_cast<const float4*>(&g_h2[i * C2]);
    float4 a = h4[0], b = h4[1];
    acc += a.x * Wl[0] + a.y * Wl[1] + a.z * Wl[2] + a.w * Wl[3]
         + b.x * Wl[4] + b.y * Wl[5] + b.z * Wl[6] + b.w * Wl[7];
    g_z[i] = 1.0f / (1.0f + expf(-acc));
}

// K8: pred[p] = z[pe[p,0]] * z[pe[p,1]]
__global__ void k_pred(const int* __restrict__ pe,
                       float* __restrict__ out, int P) {
    int p = blockIdx.x * blockDim.x + threadIdx.x;
    if (p >= P) return;
    int2 ab = reinterpret_cast<const int2*>(pe)[p];
    out[p] = g_z[ab.x] * g_z[ab.y];
}

extern "C" void kernel_launch(void* const* d_in, const int* in_sizes, int n_in,
                              void* d_out, int out_size) {
    const float* x   = (const float*)d_in[0];
    const int*   ei  = (const int*)d_in[1];
    const int*   pe  = (const int*)d_in[2];
    const float* W1  = (const float*)d_in[3];
    const float* b1  = (const float*)d_in[4];
    const float* W2  = (const float*)d_in[5];
    const float* b2  = (const float*)d_in[6];
    const float* Wl  = (const float*)d_in[7];
    const float* bl  = (const float*)d_in[8];
    float* out = (float*)d_out;

    int n = in_sizes[0] / FIN;
    int E = in_sizes[1] / 2;
    int P = in_sizes[2] / 2;
    if (E > EMAX) E = EMAX;  // g_w capacity (spec: E = 3.2M exactly)

    const int* src = ei;
    const int* dst = ei + E;

    const int T = 256;

    k_init <<<(n + T - 1) / T, T>>>(n);
    k_deg  <<<(E / 4 + T - 1) / T, T>>>(dst, E);
    k_gemm1<<<(n + NPB - 1) / NPB, 256>>>(x, W1, b1, n);
    k_scat1<<<(E + T - 1) / T, T>>>(src, dst, E);
    k_gemm2<<<(n + T - 1) / T, T>>>(W2, b2, n);
    k_scat2<<<(E + T - 1) / T, T>>>(src, dst, E);
    k_head <<<(n + T - 1) / T, T>>>(Wl, bl, n);
    k_pred <<<(P + T - 1) / T, T>>>(pe, out, P);
}

// round 6
// speedup vs baseline: 1.8487x; 1.2925x over previous
#include <cuda_runtime.h>
#include <math.h>

#define NMAX  100000
#define EMAX  3200000
#define FIN   128
#define C1    16
#define C2    8
#define NPB   64

// Scratch (device globals; 16B-aligned for float4 access)
__device__ __align__(16) float g_deg [NMAX];
__device__ __align__(16) float g_dinv[NMAX];
__device__ __align__(16) float g_s   [NMAX];       // sum of dinv[src] per dst
__device__ __align__(16) float g_w   [EMAX];       // per-edge norm weight
__device__ __align__(16) float g_u   [NMAX * C2];  // u = x @ M
__device__ __align__(16) float g_v   [NMAX * C2];  // v = A_hat u
__device__ __align__(16) float g_g   [NMAX * C2];  // g = A_hat v
__device__ __align__(16) float g_z   [NMAX];
__device__ __align__(16) float g_M   [FIN * C2];   // W1 @ W2
__device__ float g_alpha, g_beta;

// Vectorized fp32 reduction (sm_90+): one 16B RED, no return.
__device__ __forceinline__ void red_add_v4(float* addr, float a, float b,
                                           float c, float d) {
    asm volatile(
        "{\n\t"
        ".reg .u64 ga;\n\t"
        "cvta.to.global.u64 ga, %0;\n\t"
        "red.global.add.v4.f32 [ga], {%1, %2, %3, %4};\n\t"
        "}"
        :: "l"(addr), "f"(a), "f"(b), "f"(c), "f"(d) : "memory");
}

// ---------------------------------------------------------------------------
// K0: zero per-node accumulators
__global__ void k_init(int n) {
    int i = blockIdx.x * blockDim.x + threadIdx.x;
    if (i < n) { g_deg[i] = 0.0f; g_s[i] = 0.0f; }
}

// K0b: fold weights. M = W1@W2; alpha = (W2^T b1)·Wl; beta = b2·Wl + bl
__global__ void k_prep(const float* __restrict__ W1, const float* __restrict__ b1,
                       const float* __restrict__ W2, const float* __restrict__ b2,
                       const float* __restrict__ Wl, const float* __restrict__ bl) {
    int t = blockIdx.x * blockDim.x + threadIdx.x;
    if (t < FIN * C2) {
        int r = t >> 3, c = t & 7;
        float acc = 0.0f;
#pragma unroll
        for (int j = 0; j < C1; j++) acc += W1[r * C1 + j] * W2[j * C2 + c];
        g_M[t] = acc;
    }
    if (t == 0) {
        float alpha = 0.0f, beta = bl[0];
#pragma unroll
        for (int k = 0; k < C2; k++) {
            float ck = 0.0f;
#pragma unroll
            for (int j = 0; j < C1; j++) ck += b1[j] * W2[j * C2 + k];
            alpha += ck * Wl[k];
            beta  += b2[k] * Wl[k];
        }
        g_alpha = alpha;
        g_beta  = beta;
    }
}

// K1: degree scatter, 4 edges/thread via int4
__global__ void k_deg(const int* __restrict__ dst, int E) {
    int t = blockIdx.x * blockDim.x + threadIdx.x;
    int e0 = t * 4;
    if (e0 + 3 < E) {
        int4 d4 = reinterpret_cast<const int4*>(dst)[t];
        atomicAdd(&g_deg[d4.x], 1.0f);
        atomicAdd(&g_deg[d4.y], 1.0f);
        atomicAdd(&g_deg[d4.z], 1.0f);
        atomicAdd(&g_deg[d4.w], 1.0f);
    } else {
        for (int e = e0; e < E; e++) atomicAdd(&g_deg[dst[e]], 1.0f);
    }
}

// K2: u = x @ M  [N,8]; v = dinv^2 * u (self-loop seed); emits g_dinv.
// Warp = 8 nodes x 4 lanes; lane q owns channels 2q..2q+1. Padded smem tile.
#define XPAD 33
__global__ __launch_bounds__(256) void k_gemm_u(const float* __restrict__ x, int n) {
    __shared__ float4 xs4[NPB * XPAD];   // 33.8KB
    __shared__ float2 Ms2[FIN * 4];      // 4KB: Ms2[k*4+q] = M[k][2q..2q+1]

    for (int t = threadIdx.x; t < FIN * 4; t += 256)
        Ms2[t] = reinterpret_cast<const float2*>(g_M)[t];

    int base = blockIdx.x * NPB;
    int rows = n - base; if (rows > NPB) rows = NPB;

    const float4* xg = reinterpret_cast<const float4*>(x + (size_t)base * FIN);
    int total4 = rows * (FIN / 4);
    for (int t = threadIdx.x; t < total4; t += 256)
        xs4[(t >> 5) * XPAD + (t & 31)] = xg[t];
    __syncthreads();

    int j = threadIdx.x >> 2;   // node within tile
    int q = threadIdx.x & 3;    // channel pair
    float2 acc = make_float2(0.f, 0.f);

    const float4* xr = &xs4[j * XPAD];
#pragma unroll
    for (int k4 = 0; k4 < FIN / 4; k4++) {
        float4 v = xr[k4];
        float2 m0 = Ms2[(k4 * 4 + 0) * 4 + q];
        float2 m1 = Ms2[(k4 * 4 + 1) * 4 + q];
        float2 m2 = Ms2[(k4 * 4 + 2) * 4 + q];
        float2 m3 = Ms2[(k4 * 4 + 3) * 4 + q];
        acc.x += v.x * m0.x + v.y * m1.x + v.z * m2.x + v.w * m3.x;
        acc.y += v.x * m0.y + v.y * m1.y + v.z * m2.y + v.w * m3.y;
    }

    if (j < rows) {
        int i = base + j;
        float dv = rsqrtf(g_deg[i] + 1.0f);
        if (q == 0) g_dinv[i] = dv;
        float w = dv * dv;
        reinterpret_cast<float2*>(g_u)[i * 4 + q] = acc;
        reinterpret_cast<float2*>(g_v)[i * 4 + q] =
            make_float2(w * acc.x, w * acc.y);
    }
}

// K3: agg layer 1 — v[d] += w * u[s]; also emits g_w[e] and s-RED
__global__ void k_agg1(const int* __restrict__ src,
                       const int* __restrict__ dst, int E) {
    int e = blockIdx.x * blockDim.x + threadIdx.x;
    if (e >= E) return;
    int s = src[e];
    int d = dst[e];
    float ds = g_dinv[s];
    float w  = ds * g_dinv[d];
    g_w[e] = w;
    atomicAdd(&g_s[d], ds);
    const float4* us = reinterpret_cast<const float4*>(&g_u[s * C2]);
    float4 a = us[0], b = us[1];
    float* vd = &g_v[d * C2];
    red_add_v4(vd,     w * a.x, w * a.y, w * a.z, w * a.w);
    red_add_v4(vd + 4, w * b.x, w * b.y, w * b.z, w * b.w);
}

// K4: self-loop seed for layer 2: g = dinv^2 * v (v final after agg1)
__global__ void k_mid(int n) {
    int i = blockIdx.x * blockDim.x + threadIdx.x;
    if (i >= n) return;
    float dv = g_dinv[i];
    float w  = dv * dv;
    const float4* vv = reinterpret_cast<const float4*>(&g_v[i * C2]);
    float4 a = vv[0], b = vv[1];
    float4* gg = reinterpret_cast<float4*>(&g_g[i * C2]);
    gg[0] = make_float4(w * a.x, w * a.y, w * a.z, w * a.w);
    gg[1] = make_float4(w * b.x, w * b.y, w * b.z, w * b.w);
}

// K5: agg layer 2 — g[d] += w * v[s]
__global__ void k_agg2(const int* __restrict__ src,
                       const int* __restrict__ dst, int E) {
    int e = blockIdx.x * blockDim.x + threadIdx.x;
    if (e >= E) return;
    int s = src[e];
    int d = dst[e];
    float w = g_w[e];
    const float4* vs = reinterpret_cast<const float4*>(&g_v[s * C2]);
    float4 a = vs[0], b = vs[1];
    float* gd = &g_g[d * C2];
    red_add_v4(gd,     w * a.x, w * a.y, w * a.z, w * a.w);
    red_add_v4(gd + 4, w * b.x, w * b.y, w * b.z, w * b.w);
}

// K6: z = sigmoid(g·Wl + sfull*alpha + beta), sfull = dinv*g_s + dinv^2
__global__ void k_head(const float* __restrict__ Wl, int n) {
    int i = blockIdx.x * blockDim.x + threadIdx.x;
    if (i >= n) return;
    float dv = g_dinv[i];
    float sfull = dv * g_s[i] + dv * dv;
    const float4* h4 = reinterpret_cast<const float4*>(&g_g[i * C2]);
    float4 a = h4[0], b = h4[1];
    float acc = g_beta + sfull * g_alpha
              + a.x * Wl[0] + a.y * Wl[1] + a.z * Wl[2] + a.w * Wl[3]
              + b.x * Wl[4] + b.y * Wl[5] + b.z * Wl[6] + b.w * Wl[7];
    g_z[i] = 1.0f / (1.0f + expf(-acc));
}

// K7: pred[p] = z[pe[p,0]] * z[pe[p,1]]
__global__ void k_pred(const int* __restrict__ pe,
                       float* __restrict__ out, int P) {
    int p = blockIdx.x * blockDim.x + threadIdx.x;
    if (p >= P) return;
    int2 ab = reinterpret_cast<const int2*>(pe)[p];
    out[p] = g_z[ab.x] * g_z[ab.y];
}

extern "C" void kernel_launch(void* const* d_in, const int* in_sizes, int n_in,
                              void* d_out, int out_size) {
    const float* x   = (const float*)d_in[0];
    const int*   ei  = (const int*)d_in[1];
    const int*   pe  = (const int*)d_in[2];
    const float* W1  = (const float*)d_in[3];
    const float* b1  = (const float*)d_in[4];
    const float* W2  = (const float*)d_in[5];
    const float* b2  = (const float*)d_in[6];
    const float* Wl  = (const float*)d_in[7];
    const float* bl  = (const float*)d_in[8];
    float* out = (float*)d_out;

    int n = in_sizes[0] / FIN;
    int E = in_sizes[1] / 2;
    int P = in_sizes[2] / 2;
    if (E > EMAX) E = EMAX;

    const int* src = ei;
    const int* dst = ei + E;

    const int T = 256;

    k_init  <<<(n + T - 1) / T, T>>>(n);
    k_prep  <<<(FIN * C2 + T - 1) / T, T>>>(W1, b1, W2, b2, Wl, bl);
    k_deg   <<<(E / 4 + T - 1) / T, T>>>(dst, E);
    k_gemm_u<<<(n + NPB - 1) / NPB, 256>>>(x, n);
    k_agg1  <<<(E + T - 1) / T, T>>>(src, dst, E);
    k_mid   <<<(n + T - 1) / T, T>>>(n);
    k_agg2  <<<(E + T - 1) / T, T>>>(src, dst, E);
    k_head  <<<(n + T - 1) / T, T>>>(Wl, n);
    k_pred  <<<(P + T - 1) / T, T>>>(pe, out, P);
}

// round 8
// speedup vs baseline: 1.8969x; 1.0261x over previous
#include <cuda_runtime.h>
#include <cstdint>
#include <math.h>

#define NMAX  100000
#define EMAX  3200000
#define FIN   128
#define C1    16
#define C2    8
#define NPB   64

// Scratch (device globals; 16B-aligned for float4 access)
__device__ __align__(16) float g_deg [NMAX];
__device__ __align__(16) float g_dinv[NMAX];
__device__ __align__(16) float g_s   [NMAX];       // sum of dinv[src] per dst
__device__ __align__(16) float g_w   [EMAX];       // per-edge norm weight
__device__ __align__(16) float g_u   [NMAX * C2];  // u = x @ M
__device__ __align__(16) float g_v   [NMAX * C2];  // v = A_hat u
__device__ __align__(16) float g_g   [NMAX * C2];  // g = A_hat v
__device__ __align__(16) float g_z   [NMAX];
__device__ __align__(16) float g_M   [FIN * C2];   // W1 @ W2
__device__ float g_alpha, g_beta;

// Vectorized fp32 reduction (sm_90+): one 16B RED, no return.
__device__ __forceinline__ void red_add_v4(float* addr, float a, float b,
                                           float c, float d) {
    asm volatile(
        "{\n\t"
        ".reg .u64 ga;\n\t"
        "cvta.to.global.u64 ga, %0;\n\t"
        "red.global.add.v4.f32 [ga], {%1, %2, %3, %4};\n\t"
        "}"
        :: "l"(addr), "f"(a), "f"(b), "f"(c), "f"(d) : "memory");
}

__device__ __forceinline__ void cp_async16(unsigned int saddr, const void* gaddr) {
    asm volatile("cp.async.cg.shared.global [%0], [%1], 16;\n"
                 :: "r"(saddr), "l"(gaddr) : "memory");
}

// ---------------------------------------------------------------------------
// K0: zero per-node accumulators + fold weights (fused)
// M = W1@W2; alpha = (W2^T b1)·Wl; beta = b2·Wl + bl
__global__ void k_init(const float* __restrict__ W1, const float* __restrict__ b1,
                       const float* __restrict__ W2, const float* __restrict__ b2,
                       const float* __restrict__ Wl, const float* __restrict__ bl,
                       int n) {
    int t = blockIdx.x * blockDim.x + threadIdx.x;
    if (t < n) { g_deg[t] = 0.0f; g_s[t] = 0.0f; }
    if (t < FIN * C2) {
        int r = t >> 3, c = t & 7;
        float acc = 0.0f;
#pragma unroll
        for (int j = 0; j < C1; j++) acc += W1[r * C1 + j] * W2[j * C2 + c];
        g_M[t] = acc;
    }
    if (t == 0) {
        float alpha = 0.0f, beta = bl[0];
#pragma unroll
        for (int k = 0; k < C2; k++) {
            float ck = 0.0f;
#pragma unroll
            for (int j = 0; j < C1; j++) ck += b1[j] * W2[j * C2 + k];
            alpha += ck * Wl[k];
            beta  += b2[k] * Wl[k];
        }
        g_alpha = alpha;
        g_beta  = beta;
    }
}

// K1: degree scatter, 4 edges/thread via int4
__global__ void k_deg(const int* __restrict__ dst, int E) {
    int t = blockIdx.x * blockDim.x + threadIdx.x;
    int e0 = t * 4;
    if (e0 + 3 < E) {
        int4 d4 = reinterpret_cast<const int4*>(dst)[t];
        atomicAdd(&g_deg[d4.x], 1.0f);
        atomicAdd(&g_deg[d4.y], 1.0f);
        atomicAdd(&g_deg[d4.z], 1.0f);
        atomicAdd(&g_deg[d4.w], 1.0f);
    } else {
        for (int e = e0; e < E; e++) atomicAdd(&g_deg[dst[e]], 1.0f);
    }
}

// K2: u = x @ M  [N,8]; v = dinv^2 * u (self-loop seed); emits g_dinv.
// cp.async tile staging; repacked M (2 LDS.128 per k4 instead of 4 LDS.64).
#define XPAD 33
#define MQ   33   // q stride (32 k4-groups + 1 pad) in 4-float2 units
__global__ __launch_bounds__(256) void k_gemm_u(const float* __restrict__ x, int n) {
    __shared__ float4 xs4[NPB * XPAD];        // 33.8KB
    __shared__ float2 Mp[4 * MQ * 4];         // 4.2KB  Mp[(q*MQ+k4)*4+i]

    // pack M: Mp[(q*MQ + (k>>2))*4 + (k&3)] = (M[k][2q], M[k][2q+1])
    for (int t = threadIdx.x; t < FIN * 4; t += 256) {
        int k = t >> 2, q = t & 3;
        Mp[(q * MQ + (k >> 2)) * 4 + (k & 3)] =
            make_float2(g_M[k * C2 + 2 * q], g_M[k * C2 + 2 * q + 1]);
    }

    int base = blockIdx.x * NPB;
    int rows = n - base; if (rows > NPB) rows = NPB;

    // async coalesced tile load, padded smem layout
    const float4* xg = reinterpret_cast<const float4*>(x + (size_t)base * FIN);
    unsigned int xs_base = (unsigned int)__cvta_generic_to_shared(xs4);
    int total4 = rows * (FIN / 4);
#pragma unroll
    for (int t = threadIdx.x; t < total4; t += 256)
        cp_async16(xs_base + (unsigned int)(((t >> 5) * XPAD + (t & 31)) * 16), xg + t);
    asm volatile("cp.async.commit_group;\n" ::: "memory");
    asm volatile("cp.async.wait_group 0;\n" ::: "memory");
    __syncthreads();

    int j = threadIdx.x >> 2;   // node within tile
    int q = threadIdx.x & 3;    // channel pair
    float2 acc = make_float2(0.f, 0.f);

    const float4* xr = &xs4[j * XPAD];
    const float4* mq = reinterpret_cast<const float4*>(&Mp[q * MQ * 4]);
#pragma unroll
    for (int k4 = 0; k4 < FIN / 4; k4++) {
        float4 v  = xr[k4];
        float4 mA = mq[k4 * 2 + 0];   // (m0.x m0.y m1.x m1.y)
        float4 mB = mq[k4 * 2 + 1];   // (m2.x m2.y m3.x m3.y)
        acc.x += v.x * mA.x + v.y * mA.z + v.z * mB.x + v.w * mB.z;
        acc.y += v.x * mA.y + v.y * mA.w + v.z * mB.y + v.w * mB.w;
    }

    if (j < rows) {
        int i = base + j;
        float dv = rsqrtf(g_deg[i] + 1.0f);
        if (q == 0) g_dinv[i] = dv;
        float w = dv * dv;
        reinterpret_cast<float2*>(g_u)[i * 4 + q] = acc;
        reinterpret_cast<float2*>(g_v)[i * 4 + q] =
            make_float2(w * acc.x, w * acc.y);
    }
}

// K3: agg layer 1 — v[d] += w * u[s]; also emits g_w[e] and s-RED
__global__ void k_agg1(const int* __restrict__ src,
                       const int* __restrict__ dst, int E) {
    int e = blockIdx.x * blockDim.x + threadIdx.x;
    if (e >= E) return;
    int s = src[e];
    int d = dst[e];
    float ds = g_dinv[s];
    float w  = ds * g_dinv[d];
    g_w[e] = w;
    atomicAdd(&g_s[d], ds);
    const float4* us = reinterpret_cast<const float4*>(&g_u[s * C2]);
    float4 a = us[0], b = us[1];
    float* vd = &g_v[d * C2];
    red_add_v4(vd,     w * a.x, w * a.y, w * a.z, w * a.w);
    red_add_v4(vd + 4, w * b.x, w * b.y, w * b.z, w * b.w);
}

// K4: self-loop seed for layer 2: g = dinv^2 * v (v final after agg1)
__global__ void k_mid(int n) {
    int i = blockIdx.x * blockDim.x + threadIdx.x;
    if (i >= n) return;
    float dv = g_dinv[i];
    float w  = dv * dv;
    const float4* vv = reinterpret_cast<const float4*>(&g_v[i * C2]);
    float4 a = vv[0], b = vv[1];
    float4* gg = reinterpret_cast<float4*>(&g_g[i * C2]);
    gg[0] = make_float4(w * a.x, w * a.y, w * a.z, w * a.w);
    gg[1] = make_float4(w * b.x, w * b.y, w * b.z, w * b.w);
}

// K5: agg layer 2 — g[d] += w * v[s]
__global__ void k_agg2(const int* __restrict__ src,
                       const int* __restrict__ dst, int E) {
    int e = blockIdx.x * blockDim.x + threadIdx.x;
    if (e >= E) return;
    int s = src[e];
    int d = dst[e];
    float w = g_w[e];
    const float4* vs = reinterpret_cast<const float4*>(&g_v[s * C2]);
    float4 a = vs[0], b = vs[1];
    float* gd = &g_g[d * C2];
    red_add_v4(gd,     w * a.x, w * a.y, w * a.z, w * a.w);
    red_add_v4(gd + 4, w * b.x, w * b.y, w * b.z, w * b.w);
}

// K6: z = sigmoid(g·Wl + sfull*alpha + beta), sfull = dinv*g_s + dinv^2
__global__ void k_head(const float* __restrict__ Wl, int n) {
    int i = blockIdx.x * blockDim.x + threadIdx.x;
    if (i >= n) return;
    float dv = g_dinv[i];
    float sfull = dv * g_s[i] + dv * dv;
    const float4* h4 = reinterpret_cast<const float4*>(&g_g[i * C2]);
    float4 a = h4[0], b = h4[1];
    float acc = g_beta + sfull * g_alpha
              + a.x * Wl[0] + a.y * Wl[1] + a.z * Wl[2] + a.w * Wl[3]
              + b.x * Wl[4] + b.y * Wl[5] + b.z * Wl[6] + b.w * Wl[7];
    g_z[i] = 1.0f / (1.0f + expf(-acc));
}

// K7: pred[p] = z[pe[p,0]] * z[pe[p,1]]
__global__ void k_pred(const int* __restrict__ pe,
                       float* __restrict__ out, int P) {
    int p = blockIdx.x * blockDim.x + threadIdx.x;
    if (p >= P) return;
    int2 ab = reinterpret_cast<const int2*>(pe)[p];
    out[p] = g_z[ab.x] * g_z[ab.y];
}

extern "C" void kernel_launch(void* const* d_in, const int* in_sizes, int n_in,
                              void* d_out, int out_size) {
    const float* x   = (const float*)d_in[0];
    const int*   ei  = (const int*)d_in[1];
    const int*   pe  = (const int*)d_in[2];
    const float* W1  = (const float*)d_in[3];
    const float* b1  = (const float*)d_in[4];
    const float* W2  = (const float*)d_in[5];
    const float* b2  = (const float*)d_in[6];
    const float* Wl  = (const float*)d_in[7];
    const float* bl  = (const float*)d_in[8];
    float* out = (float*)d_out;

    int n = in_sizes[0] / FIN;
    int E = in_sizes[1] / 2;
    int P = in_sizes[2] / 2;
    if (E > EMAX) E = EMAX;

    const int* src = ei;
    const int* dst = ei + E;

    const int T = 256;

    k_init  <<<(n + T - 1) / T, T>>>(W1, b1, W2, b2, Wl, bl, n);
    k_deg   <<<(E / 4 + T - 1) / T, T>>>(dst, E);
    k_gemm_u<<<(n + NPB - 1) / NPB, 256>>>(x, n);
    k_agg1  <<<(E + T - 1) / T, T>>>(src, dst, E);
    k_mid   <<<(n + T - 1) / T, T>>>(n);
    k_agg2  <<<(E + T - 1) / T, T>>>(src, dst, E);
    k_head  <<<(n + T - 1) / T, T>>>(Wl, n);
    k_pred  <<<(P + T - 1) / T, T>>>(pe, out, P);
}